// round 6
// baseline (speedup 1.0000x reference)
#include <cuda_runtime.h>
#include <cuda_fp16.h>
#include <cstdint>

#define S_TOK 4096
#define MDIM  1024
#define NEXP  8
#define CAP   1024

#define BM 128
#define BN 128
#define BK 32
#define NST 4

#define A_BYTES  (BM * 64)          // 128 rows x 32 fp16, 64B swizzled rows
#define BF_BYTES (BK * 528)         // 32 rows x 132 f32 (528B padded rows)
#define STG_BYTES (A_BYTES + BF_BYTES)          // 25088
#define BH_OFF   (NST * STG_BYTES)              // fp16 B buffer: 32 x 272B
#define BH_BYTES (BK * 272)                     // 8704
#define TOK_OFF  (BH_OFF + BH_BYTES)            // 109056
#define SMEM_DYN (TOK_OFF + 1024)               // 110080

// ---------------- scratch ----------------------------------------------------
__device__ int    g_idx0[S_TOK];
__device__ float  g_wtop[S_TOK];
__device__ float  g_gates[S_TOK * NEXP];
__device__ int    g_perm[NEXP * CAP];
__device__ int    g_cnt[NEXP];
__device__ __half g_xh[S_TOK * MDIM];   // fp16 x (8MB), written by gate

// ---------------- helpers ---------------------------------------------------
__device__ __forceinline__ uint32_t smem_u32(const void* p) {
    uint32_t a;
    asm("{ .reg .u64 t; cvta.to.shared.u64 t, %1; cvt.u32.u64 %0, t; }" : "=r"(a) : "l"(p));
    return a;
}

#define CP_ASYNC16(dst, src) \
    asm volatile("cp.async.cg.shared.global [%0], [%1], 16;" :: "r"(dst), "l"(src) : "memory")
#define CP_COMMIT() asm volatile("cp.async.commit_group;" ::: "memory")
#define CP_WAIT2()  asm volatile("cp.async.wait_group 2;" ::: "memory")

#define LDSM_X4(r0, r1, r2, r3, addr)                                          \
    asm volatile("ldmatrix.sync.aligned.m8n8.x4.shared.b16 {%0,%1,%2,%3}, [%4];" \
        : "=r"(r0), "=r"(r1), "=r"(r2), "=r"(r3) : "r"(addr))
#define LDSM_X4_T(r0, r1, r2, r3, addr)                                        \
    asm volatile("ldmatrix.sync.aligned.m8n8.x4.trans.shared.b16 {%0,%1,%2,%3}, [%4];" \
        : "=r"(r0), "=r"(r1), "=r"(r2), "=r"(r3) : "r"(addr))

#define MMA_F16(c, a, b)                                                       \
    asm volatile(                                                              \
        "mma.sync.aligned.m16n8k16.row.col.f32.f16.f16.f32 "                   \
        "{%0,%1,%2,%3},{%4,%5,%6,%7},{%8,%9},{%0,%1,%2,%3};\n"                 \
        : "+f"((c)[0]), "+f"((c)[1]), "+f"((c)[2]), "+f"((c)[3])               \
        : "r"((a)[0]), "r"((a)[1]), "r"((a)[2]), "r"((a)[3]),                  \
          "r"((b)[0]), "r"((b)[1]))

// ---------------- kernel 1: gating (2 tokens/warp, writes fp16 x) ------------
__global__ void gate_kernel(const float* __restrict__ x,
                            const float* __restrict__ wg) {
    int tid = threadIdx.x;
    int warp = tid >> 5, lane = tid & 31;
    int s0 = blockIdx.x * 16 + warp * 2;

    float acc[NEXP][2];
#pragma unroll
    for (int e = 0; e < NEXP; e++) { acc[e][0] = 0.f; acc[e][1] = 0.f; }

    const float4* xr0 = reinterpret_cast<const float4*>(x + (size_t)s0 * MDIM);
    const float4* xr1 = reinterpret_cast<const float4*>(x + (size_t)(s0 + 1) * MDIM);
    uint2* xo0 = reinterpret_cast<uint2*>(g_xh + (size_t)s0 * MDIM);
    uint2* xo1 = reinterpret_cast<uint2*>(g_xh + (size_t)(s0 + 1) * MDIM);
#pragma unroll
    for (int i = 0; i < 8; i++) {
        int k4 = i * 32 + lane;
        float4 x0 = xr0[k4], x1 = xr1[k4];
        {
            __half2 a0 = __floats2half2_rn(x0.x, x0.y);
            __half2 b0 = __floats2half2_rn(x0.z, x0.w);
            uint2 p0; p0.x = *reinterpret_cast<uint32_t*>(&a0);
            p0.y = *reinterpret_cast<uint32_t*>(&b0);
            xo0[k4] = p0;
            __half2 a1 = __floats2half2_rn(x1.x, x1.y);
            __half2 b1 = __floats2half2_rn(x1.z, x1.w);
            uint2 p1; p1.x = *reinterpret_cast<uint32_t*>(&a1);
            p1.y = *reinterpret_cast<uint32_t*>(&b1);
            xo1[k4] = p1;
        }
#pragma unroll
        for (int e = 0; e < NEXP; e++) {
            float4 wv = reinterpret_cast<const float4*>(wg + e * MDIM)[k4];
            acc[e][0] += x0.x * wv.x + x0.y * wv.y + x0.z * wv.z + x0.w * wv.w;
            acc[e][1] += x1.x * wv.x + x1.y * wv.y + x1.z * wv.z + x1.w * wv.w;
        }
    }
#pragma unroll
    for (int e = 0; e < NEXP; e++) {
#pragma unroll
        for (int off = 16; off > 0; off >>= 1) {
            acc[e][0] += __shfl_xor_sync(0xffffffffu, acc[e][0], off);
            acc[e][1] += __shfl_xor_sync(0xffffffffu, acc[e][1], off);
        }
    }

    if (lane < 2) {
        int s = s0 + lane;
        float a[NEXP];
#pragma unroll
        for (int e = 0; e < NEXP; e++) a[e] = acc[e][lane];
        float mx = a[0];
        int am = 0;
#pragma unroll
        for (int e = 1; e < NEXP; e++)
            if (a[e] > mx) { mx = a[e]; am = e; }
        float g[NEXP];
        float sum = 0.f;
#pragma unroll
        for (int e = 0; e < NEXP; e++) { g[e] = expf(a[e] - mx); sum += g[e]; }
        float inv = 1.f / sum;
        g_idx0[s] = am;
        g_wtop[s] = g[am] * inv;
#pragma unroll
        for (int e = 0; e < NEXP; e++) g_gates[s * NEXP + e] = g[e] * inv;
    }
}

// ---------------- kernel 2: scan + perm + loss + drop-zero -------------------
__global__ void scan_kernel(float* __restrict__ out, int write_loss) {
    __shared__ unsigned char sidx[S_TOK];
    __shared__ int counts[256][9];
    __shared__ float mesh[256][9];
    __shared__ float me_f[NEXP];
    __shared__ int raw_cnt[NEXP];
    __shared__ int droplist[64];
    __shared__ int sh_drop;
    int tid = threadIdx.x;
    int wid = tid >> 5, lane = tid & 31;
    if (tid == 0) sh_drop = 0;

    for (int i = tid; i < S_TOK; i += 256)
        sidx[i] = (unsigned char)g_idx0[i];

    {
        float me8[NEXP];
#pragma unroll
        for (int e = 0; e < NEXP; e++) me8[e] = 0.f;
        int base = tid * 16;
        for (int j = 0; j < 16; j++) {
            const float* gp = g_gates + (size_t)(base + j) * NEXP;
#pragma unroll
            for (int e = 0; e < NEXP; e++) me8[e] += gp[e];
        }
#pragma unroll
        for (int e = 0; e < NEXP; e++) mesh[tid][e] = me8[e];
    }
    __syncthreads();

    int base = tid * 16;
    {
        int c8[NEXP];
#pragma unroll
        for (int e = 0; e < NEXP; e++) c8[e] = 0;
#pragma unroll
        for (int j = 0; j < 16; j++) c8[sidx[base + j]]++;
#pragma unroll
        for (int e = 0; e < NEXP; e++) counts[tid][e] = c8[e];
    }
    __syncthreads();

    {
        int e = wid;
        int run = 0;
        float msum = 0.f;
#pragma unroll
        for (int c = 0; c < 8; c++) {
            int t = c * 32 + lane;
            int v = counts[t][e];
            msum += mesh[t][e];
            int s = v;
#pragma unroll
            for (int off = 1; off < 32; off <<= 1) {
                int n = __shfl_up_sync(0xffffffffu, s, off);
                if (lane >= off) s += n;
            }
            counts[t][e] = run + s - v;
            run += __shfl_sync(0xffffffffu, s, 31);
        }
#pragma unroll
        for (int off = 16; off > 0; off >>= 1)
            msum += __shfl_xor_sync(0xffffffffu, msum, off);
        if (lane == 0) {
            raw_cnt[e] = run;
            g_cnt[e] = run < CAP ? run : CAP;
            me_f[e] = msum;
        }
    }
    __syncthreads();

    {
        int off[NEXP];
#pragma unroll
        for (int e = 0; e < NEXP; e++) off[e] = counts[tid][e];
#pragma unroll
        for (int j = 0; j < 16; j++) {
            int s2 = base + j;
            int e = sidx[s2];
            int c = off[e]++;
            if (c < CAP) {
                g_perm[e * CAP + c] = s2;
            } else {
                int p = atomicAdd(&sh_drop, 1);
                if (p < 64) droplist[p] = s2;
            }
        }
    }
    __syncthreads();

    if (tid == 0 && write_loss) {
        float l = 0.f;
#pragma unroll
        for (int e = 0; e < NEXP; e++) l += me_f[e] * (float)raw_cnt[e];
        out[(size_t)S_TOK * MDIM] =
            l * ((float)NEXP / ((float)S_TOK * (float)S_TOK));
    }

    int nd = sh_drop < 64 ? sh_drop : 64;
    for (int i = 0; i < nd; i++) {
        float* row = out + (size_t)droplist[i] * MDIM;
        float4 z = make_float4(0.f, 0.f, 0.f, 0.f);
        for (int j = tid; j < MDIM / 4; j += 256)
            reinterpret_cast<float4*>(row)[j] = z;
    }
}

// ---------------- kernel 3: gathered grouped GEMM (fp16 HMMA, in-GEMM cvt) ---
__global__ void __launch_bounds__(256, 2)
moe_gemm(const float* __restrict__ we, float* __restrict__ out) {
    extern __shared__ char smem[];
    int*   toks = reinterpret_cast<int*>(smem + TOK_OFF);
    float* wsh  = reinterpret_cast<float*>(smem + TOK_OFF + 512);

    int e = blockIdx.z, rt = blockIdx.y;
    int count = g_cnt[e];
    if (rt * BM >= count) return;
    int nb = blockIdx.x * BN;
    int tid = threadIdx.x;

    if (tid < BM) {
        int slot = rt * BM + tid;
        int s = (slot < count) ? g_perm[e * CAP + slot] : 0;
        toks[tid] = s;
        wsh[tid] = (slot < count) ? g_wtop[s] : 0.f;
    }
    __syncthreads();

    const float* weB = we + (size_t)e * MDIM * MDIM;
    uint32_t smA = smem_u32(smem);
    uint32_t Bh = smA + BH_OFF;

    int atok[2];
#pragma unroll
    for (int p = 0; p < 2; p++) atok[p] = toks[(tid >> 2) + 64 * p];

    // cp.async per stage: 6 chunks of 16B per thread
    //  i<2 : A fp16 chunk (m = u>>2, q = u&3) -> 64B swizzled rows
    //  i>=2: B f32 chunk  (k = v>>5, j = v&31) -> 528B padded rows
    auto issue_stage = [&](int kt, int st) {
        uint32_t Ab = smA + (uint32_t)(st * STG_BYTES);
        uint32_t Bf = Ab + A_BYTES;
        int k0 = kt * BK;
#pragma unroll
        for (int i = 0; i < 6; i++) {
            int u = tid + 256 * i;
            if (i < 2) {
                int m = u >> 2, q = u & 3;
                const __half* src = g_xh + (size_t)atok[i] * MDIM + k0 + q * 8;
                uint32_t dst = Ab + (uint32_t)(m * 64) +
                               (uint32_t)((q ^ ((m >> 1) & 3)) << 4);
                CP_ASYNC16(dst, src);
            } else {
                int v = u - 512;
                int k = v >> 5, j = v & 31;
                const float* src = weB + (size_t)(k0 + k) * MDIM + nb + j * 4;
                uint32_t dst = Bf + (uint32_t)(k * 528 + j * 16);
                CP_ASYNC16(dst, src);
            }
        }
    };

    int warp = tid >> 5, lane = tid & 31;
    int gid = lane >> 2, tg = lane & 3;
    int wr = (warp & 1) * 64;
    int wc = (warp >> 1) * 32;
    int lane15 = lane & 15, lhi = lane >> 4;

    // B converter mapping: thread -> (k row, 16 floats starting at n0)
    int ck = tid >> 3;
    int cn0 = (tid & 7) * 16;

    float acc[4][4][4];
#pragma unroll
    for (int mi = 0; mi < 4; mi++)
#pragma unroll
        for (int ni = 0; ni < 4; ni++)
#pragma unroll
            for (int r = 0; r < 4; r++) acc[mi][ni][r] = 0.f;

    const int NKT = MDIM / BK;   // 32

    issue_stage(0, 0); CP_COMMIT();
    issue_stage(1, 1); CP_COMMIT();
    issue_stage(2, 2); CP_COMMIT();

    for (int kt = 0; kt < NKT; kt++) {
        CP_WAIT2();
        __syncthreads();          // stage kt ready; prior tile's LDSM/LDS done
        if (kt + 3 < NKT) issue_stage(kt + 3, (kt + 3) & (NST - 1));
        CP_COMMIT();

        int st = kt & (NST - 1);
        uint32_t Ab = smA + (uint32_t)(st * STG_BYTES);
        const float* Bf = reinterpret_cast<const float*>(
            smem + st * STG_BYTES + A_BYTES);

        // convert B f32 -> fp16 buffer (each thread: 16 floats of row ck)
        {
            const float4* srcr = reinterpret_cast<const float4*>(Bf + ck * 132 + cn0);
            float4 v0 = srcr[0], v1 = srcr[1], v2 = srcr[2], v3 = srcr[3];
            uint4 o0, o1;
            __half2 h;
            h = __floats2half2_rn(v0.x, v0.y); o0.x = *reinterpret_cast<uint32_t*>(&h);
            h = __floats2half2_rn(v0.z, v0.w); o0.y = *reinterpret_cast<uint32_t*>(&h);
            h = __floats2half2_rn(v1.x, v1.y); o0.z = *reinterpret_cast<uint32_t*>(&h);
            h = __floats2half2_rn(v1.z, v1.w); o0.w = *reinterpret_cast<uint32_t*>(&h);
            h = __floats2half2_rn(v2.x, v2.y); o1.x = *reinterpret_cast<uint32_t*>(&h);
            h = __floats2half2_rn(v2.z, v2.w); o1.y = *reinterpret_cast<uint32_t*>(&h);
            h = __floats2half2_rn(v3.x, v3.y); o1.z = *reinterpret_cast<uint32_t*>(&h);
            h = __floats2half2_rn(v3.z, v3.w); o1.w = *reinterpret_cast<uint32_t*>(&h);
            uint4* dstr = reinterpret_cast<uint4*>(smem + BH_OFF + ck * 272 + cn0 * 2);
            dstr[0] = o0;
            dstr[1] = o1;
        }
        __syncthreads();          // Bh ready

        uint32_t a[2][4][4], b[2][4][2];
        auto load_frag = [&](int ks, int buf) {
            int qq = ks * 2 + lhi;
#pragma unroll
            for (int mi = 0; mi < 4; mi++) {
                int row = wr + mi * 16 + lane15;
                uint32_t ad = Ab + (uint32_t)(row * 64) +
                              (uint32_t)((qq ^ ((row >> 1) & 3)) << 4);
                LDSM_X4(a[buf][mi][0], a[buf][mi][1], a[buf][mi][2], a[buf][mi][3], ad);
            }
#pragma unroll
            for (int ni2 = 0; ni2 < 2; ni2++) {
                uint32_t bd = Bh + (uint32_t)((ks * 16 + lane15) * 272) +
                              (uint32_t)((wc + ni2 * 16 + lhi * 8) * 2);
                LDSM_X4_T(b[buf][ni2 * 2][0], b[buf][ni2 * 2][1],
                          b[buf][ni2 * 2 + 1][0], b[buf][ni2 * 2 + 1][1], bd);
            }
        };

        load_frag(0, 0);
#pragma unroll
        for (int ks = 0; ks < 2; ks++) {
            if (ks < 1) load_frag(1, 1);
#pragma unroll
            for (int mi = 0; mi < 4; mi++)
#pragma unroll
                for (int ni = 0; ni < 4; ni++)
                    MMA_F16(acc[mi][ni], a[ks][mi], b[ks][ni]);
        }
    }

    // epilogue
#pragma unroll
    for (int mi = 0; mi < 4; mi++) {
#pragma unroll
        for (int half = 0; half < 2; half++) {
            int r = wr + mi * 16 + gid + 8 * half;
            int slot = rt * BM + r;
            if (slot < count) {
                int s = toks[r];
                float w = wsh[r];
                float* o = out + (size_t)s * MDIM + nb + wc + tg * 2;
#pragma unroll
                for (int ni = 0; ni < 4; ni++) {
                    float2 v;
                    v.x = acc[mi][ni][half * 2 + 0] * w;
                    v.y = acc[mi][ni][half * 2 + 1] * w;
                    *reinterpret_cast<float2*>(o + ni * 8) = v;
                }
            }
        }
    }
}

// ---------------- launch -----------------------------------------------------
extern "C" void kernel_launch(void* const* d_in, const int* in_sizes, int n_in,
                              void* d_out, int out_size) {
    const float* x  = (const float*)d_in[0];
    const float* wg = (const float*)d_in[1];
    const float* we = (const float*)d_in[2];
    float* out = (float*)d_out;

    cudaFuncSetAttribute(moe_gemm, cudaFuncAttributeMaxDynamicSharedMemorySize,
                         SMEM_DYN);

    gate_kernel<<<S_TOK / 16, 256>>>(x, wg);
    scan_kernel<<<1, 256>>>(out, (long)out_size > (long)S_TOK * MDIM ? 1 : 0);
    dim3 g(MDIM / BN, CAP / BM, NEXP);
    moe_gemm<<<g, 256, SMEM_DYN>>>(we, out);
}

// round 8
// speedup vs baseline: 1.2263x; 1.2263x over previous
#include <cuda_runtime.h>
#include <cuda_fp16.h>
#include <cstdint>

#define S_TOK 4096
#define MDIM  1024
#define NEXP  8
#define CAP   1024

#define BM 128
#define BN 128
#define BK 32
#define NST 4

#define A_BYTES (BM * 64)        // 128 rows x 32 fp16 (64B, swizzled)
#define B_BYTES (BK * 272)       // 32 rows x 128 fp16 + 16B pad (272B rows)
#define STG_BYTES (A_BYTES + B_BYTES)   // 16896
#define SMEM_DYN (NST * STG_BYTES + 1024)

#define GATE_BLKS 256
#define CVT_BLKS  768

// ---------------- scratch ----------------------------------------------------
__device__ int    g_idx0[S_TOK];
__device__ float  g_wtop[S_TOK];
__device__ float  g_gates[S_TOK * NEXP];
__device__ int    g_perm[NEXP * CAP];
__device__ int    g_cnt[NEXP];
__device__ __half g_xh[S_TOK * MDIM];                  // fp16 x (8MB)
__device__ __half g_weh[(size_t)NEXP * MDIM * MDIM];   // fp16 we (16MB)

// ---------------- helpers ---------------------------------------------------
__device__ __forceinline__ uint32_t smem_u32(const void* p) {
    uint32_t a;
    asm("{ .reg .u64 t; cvta.to.shared.u64 t, %1; cvt.u32.u64 %0, t; }" : "=r"(a) : "l"(p));
    return a;
}

#define CP_ASYNC16(dst, src) \
    asm volatile("cp.async.cg.shared.global [%0], [%1], 16;" :: "r"(dst), "l"(src) : "memory")
#define CP_COMMIT() asm volatile("cp.async.commit_group;" ::: "memory")
#define CP_WAIT2()  asm volatile("cp.async.wait_group 2;" ::: "memory")

#define LDSM_X4(r0, r1, r2, r3, addr)                                          \
    asm volatile("ldmatrix.sync.aligned.m8n8.x4.shared.b16 {%0,%1,%2,%3}, [%4];" \
        : "=r"(r0), "=r"(r1), "=r"(r2), "=r"(r3) : "r"(addr))
#define LDSM_X4_T(r0, r1, r2, r3, addr)                                        \
    asm volatile("ldmatrix.sync.aligned.m8n8.x4.trans.shared.b16 {%0,%1,%2,%3}, [%4];" \
        : "=r"(r0), "=r"(r1), "=r"(r2), "=r"(r3) : "r"(addr))

#define MMA_F16(c, a, b)                                                       \
    asm volatile(                                                              \
        "mma.sync.aligned.m16n8k16.row.col.f32.f16.f16.f32 "                   \
        "{%0,%1,%2,%3},{%4,%5,%6,%7},{%8,%9},{%0,%1,%2,%3};\n"                 \
        : "+f"((c)[0]), "+f"((c)[1]), "+f"((c)[2]), "+f"((c)[3])               \
        : "r"((a)[0]), "r"((a)[1]), "r"((a)[2]), "r"((a)[3]),                  \
          "r"((b)[0]), "r"((b)[1]))

// ---------------- kernel 1: fused gate (blocks 0..255) + we->fp16 (rest) -----
__global__ void gate_cvt_kernel(const float* __restrict__ x,
                                const float* __restrict__ wg,
                                const float* __restrict__ we) {
    int tid = threadIdx.x;

    if (blockIdx.x >= GATE_BLKS) {
        // ---- cvt part: grid-stride fp16 conversion of we ----
        size_t n4 = (size_t)NEXP * MDIM * MDIM / 4;
        size_t stride = (size_t)CVT_BLKS * 256;
        for (size_t i = (size_t)(blockIdx.x - GATE_BLKS) * 256 + tid; i < n4;
             i += stride) {
            float4 v = reinterpret_cast<const float4*>(we)[i];
            __half2 ha = __floats2half2_rn(v.x, v.y);
            __half2 hb = __floats2half2_rn(v.z, v.w);
            uint2 p;
            p.x = *reinterpret_cast<uint32_t*>(&ha);
            p.y = *reinterpret_cast<uint32_t*>(&hb);
            reinterpret_cast<uint2*>(g_weh)[i] = p;
        }
        return;
    }

    // ---- gate part: 2 tokens/warp, writes fp16 x ----
    int warp = tid >> 5, lane = tid & 31;
    int s0 = blockIdx.x * 16 + warp * 2;

    float acc[NEXP][2];
#pragma unroll
    for (int e = 0; e < NEXP; e++) { acc[e][0] = 0.f; acc[e][1] = 0.f; }

    const float4* xr0 = reinterpret_cast<const float4*>(x + (size_t)s0 * MDIM);
    const float4* xr1 = reinterpret_cast<const float4*>(x + (size_t)(s0 + 1) * MDIM);
    uint2* xo0 = reinterpret_cast<uint2*>(g_xh + (size_t)s0 * MDIM);
    uint2* xo1 = reinterpret_cast<uint2*>(g_xh + (size_t)(s0 + 1) * MDIM);
#pragma unroll
    for (int i = 0; i < 8; i++) {
        int k4 = i * 32 + lane;
        float4 x0 = xr0[k4], x1 = xr1[k4];
        {
            __half2 a0 = __floats2half2_rn(x0.x, x0.y);
            __half2 b0 = __floats2half2_rn(x0.z, x0.w);
            uint2 p0; p0.x = *reinterpret_cast<uint32_t*>(&a0);
            p0.y = *reinterpret_cast<uint32_t*>(&b0);
            xo0[k4] = p0;
            __half2 a1 = __floats2half2_rn(x1.x, x1.y);
            __half2 b1 = __floats2half2_rn(x1.z, x1.w);
            uint2 p1; p1.x = *reinterpret_cast<uint32_t*>(&a1);
            p1.y = *reinterpret_cast<uint32_t*>(&b1);
            xo1[k4] = p1;
        }
#pragma unroll
        for (int e = 0; e < NEXP; e++) {
            float4 wv = reinterpret_cast<const float4*>(wg + e * MDIM)[k4];
            acc[e][0] += x0.x * wv.x + x0.y * wv.y + x0.z * wv.z + x0.w * wv.w;
            acc[e][1] += x1.x * wv.x + x1.y * wv.y + x1.z * wv.z + x1.w * wv.w;
        }
    }
#pragma unroll
    for (int e = 0; e < NEXP; e++) {
#pragma unroll
        for (int off = 16; off > 0; off >>= 1) {
            acc[e][0] += __shfl_xor_sync(0xffffffffu, acc[e][0], off);
            acc[e][1] += __shfl_xor_sync(0xffffffffu, acc[e][1], off);
        }
    }

    if (lane < 2) {
        int s = s0 + lane;
        float a[NEXP];
#pragma unroll
        for (int e = 0; e < NEXP; e++) a[e] = acc[e][lane];
        float mx = a[0];
        int am = 0;
#pragma unroll
        for (int e = 1; e < NEXP; e++)
            if (a[e] > mx) { mx = a[e]; am = e; }   // first-max = lowest idx on ties
        float g[NEXP];
        float sum = 0.f;
#pragma unroll
        for (int e = 0; e < NEXP; e++) { g[e] = expf(a[e] - mx); sum += g[e]; }
        float inv = 1.f / sum;
        g_idx0[s] = am;
        g_wtop[s] = g[am] * inv;
#pragma unroll
        for (int e = 0; e < NEXP; e++) g_gates[s * NEXP + e] = g[e] * inv;
    }
}

// ---------------- kernel 2: scan + perm + loss + drop-zero -------------------
__global__ void scan_kernel(float* __restrict__ out, int write_loss) {
    __shared__ unsigned char sidx[S_TOK];
    __shared__ int counts[256][9];
    __shared__ float mesh[256][9];
    __shared__ float me_f[NEXP];
    __shared__ int raw_cnt[NEXP];
    __shared__ int droplist[64];
    __shared__ int sh_drop;
    int tid = threadIdx.x;
    int wid = tid >> 5, lane = tid & 31;
    if (tid == 0) sh_drop = 0;

    for (int i = tid; i < S_TOK; i += 256)
        sidx[i] = (unsigned char)g_idx0[i];

    {
        float me8[NEXP];
#pragma unroll
        for (int e = 0; e < NEXP; e++) me8[e] = 0.f;
        int base = tid * 16;
        for (int j = 0; j < 16; j++) {
            const float* gp = g_gates + (size_t)(base + j) * NEXP;
#pragma unroll
            for (int e = 0; e < NEXP; e++) me8[e] += gp[e];
        }
#pragma unroll
        for (int e = 0; e < NEXP; e++) mesh[tid][e] = me8[e];
    }
    __syncthreads();

    int base = tid * 16;
    {
        int c8[NEXP];
#pragma unroll
        for (int e = 0; e < NEXP; e++) c8[e] = 0;
#pragma unroll
        for (int j = 0; j < 16; j++) c8[sidx[base + j]]++;
#pragma unroll
        for (int e = 0; e < NEXP; e++) counts[tid][e] = c8[e];
    }
    __syncthreads();

    {
        int e = wid;
        int run = 0;
        float msum = 0.f;
#pragma unroll
        for (int c = 0; c < 8; c++) {
            int t = c * 32 + lane;
            int v = counts[t][e];
            msum += mesh[t][e];
            int s = v;
#pragma unroll
            for (int off = 1; off < 32; off <<= 1) {
                int n = __shfl_up_sync(0xffffffffu, s, off);
                if (lane >= off) s += n;
            }
            counts[t][e] = run + s - v;
            run += __shfl_sync(0xffffffffu, s, 31);
        }
#pragma unroll
        for (int off = 16; off > 0; off >>= 1)
            msum += __shfl_xor_sync(0xffffffffu, msum, off);
        if (lane == 0) {
            raw_cnt[e] = run;
            g_cnt[e] = run < CAP ? run : CAP;
            me_f[e] = msum;
        }
    }
    __syncthreads();

    {
        int off[NEXP];
#pragma unroll
        for (int e = 0; e < NEXP; e++) off[e] = counts[tid][e];
#pragma unroll
        for (int j = 0; j < 16; j++) {
            int s2 = base + j;
            int e = sidx[s2];
            int c = off[e]++;
            if (c < CAP) {
                g_perm[e * CAP + c] = s2;
            } else {
                int p = atomicAdd(&sh_drop, 1);
                if (p < 64) droplist[p] = s2;
            }
        }
    }
    __syncthreads();

    if (tid == 0 && write_loss) {
        float l = 0.f;
#pragma unroll
        for (int e = 0; e < NEXP; e++) l += me_f[e] * (float)raw_cnt[e];
        out[(size_t)S_TOK * MDIM] =
            l * ((float)NEXP / ((float)S_TOK * (float)S_TOK));
    }

    int nd = sh_drop < 64 ? sh_drop : 64;
    for (int i = 0; i < nd; i++) {
        float* row = out + (size_t)droplist[i] * MDIM;
        float4 z = make_float4(0.f, 0.f, 0.f, 0.f);
        for (int j = tid; j < MDIM / 4; j += 256)
            reinterpret_cast<float4*>(row)[j] = z;
    }
}

// ---------------- kernel 3: gathered grouped GEMM (fp16 HMMA, R5 version) ----
__global__ void __launch_bounds__(256, 2)
moe_gemm(float* __restrict__ out) {
    extern __shared__ char smem[];
    int*   toks = reinterpret_cast<int*>(smem + NST * STG_BYTES);
    float* wsh  = reinterpret_cast<float*>(smem + NST * STG_BYTES + 512);

    int e = blockIdx.z, rt = blockIdx.y;
    int count = g_cnt[e];
    if (rt * BM >= count) return;
    int nb = blockIdx.x * BN;
    int tid = threadIdx.x;

    if (tid < BM) {
        int slot = rt * BM + tid;
        int s = (slot < count) ? g_perm[e * CAP + slot] : 0;
        toks[tid] = s;
        wsh[tid] = (slot < count) ? g_wtop[s] : 0.f;
    }
    __syncthreads();

    const __half* weh = g_weh + (size_t)e * MDIM * MDIM;
    uint32_t smA = smem_u32(smem);

    int atok[2];
#pragma unroll
    for (int p = 0; p < 2; p++) atok[p] = toks[(tid >> 2) + 64 * p];

    auto issue_stage = [&](int kt, int st) {
        uint32_t Ab = smA + (uint32_t)(st * STG_BYTES);
        uint32_t Bb = Ab + A_BYTES;
        int k0 = kt * BK;
#pragma unroll
        for (int i = 0; i < 4; i++) {
            int u = tid + 256 * i;
            if (i < 2) {
                int m = u >> 2, q = u & 3;
                const __half* src = g_xh + (size_t)atok[i] * MDIM + k0 + q * 8;
                uint32_t dst = Ab + (uint32_t)(m * 64) +
                               (uint32_t)((q ^ ((m >> 1) & 3)) << 4);
                CP_ASYNC16(dst, src);
            } else {
                int v = u - 512;
                int k = v >> 4, j = v & 15;
                const __half* src = weh + (size_t)(k0 + k) * MDIM + nb + j * 8;
                uint32_t dst = Bb + (uint32_t)(k * 272 + j * 16);
                CP_ASYNC16(dst, src);
            }
        }
    };

    int warp = tid >> 5, lane = tid & 31;
    int gid = lane >> 2, tg = lane & 3;
    int wr = (warp & 1) * 64;
    int wc = (warp >> 1) * 32;
    int lane15 = lane & 15, lhi = lane >> 4;

    float acc[4][4][4];
#pragma unroll
    for (int mi = 0; mi < 4; mi++)
#pragma unroll
        for (int ni = 0; ni < 4; ni++)
#pragma unroll
            for (int r = 0; r < 4; r++) acc[mi][ni][r] = 0.f;

    const int NKT = MDIM / BK;   // 32

    issue_stage(0, 0); CP_COMMIT();
    issue_stage(1, 1); CP_COMMIT();
    issue_stage(2, 2); CP_COMMIT();

    for (int kt = 0; kt < NKT; kt++) {
        CP_WAIT2();
        __syncthreads();
        if (kt + 3 < NKT) issue_stage(kt + 3, (kt + 3) & (NST - 1));
        CP_COMMIT();

        int st = kt & (NST - 1);
        uint32_t Ab = smA + (uint32_t)(st * STG_BYTES);
        uint32_t Bb = Ab + A_BYTES;

        uint32_t a[2][4][4], b[2][4][2];
        auto load_frag = [&](int ks, int buf) {
            int qq = ks * 2 + lhi;
#pragma unroll
            for (int mi = 0; mi < 4; mi++) {
                int row = wr + mi * 16 + lane15;
                uint32_t ad = Ab + (uint32_t)(row * 64) +
                              (uint32_t)((qq ^ ((row >> 1) & 3)) << 4);
                LDSM_X4(a[buf][mi][0], a[buf][mi][1], a[buf][mi][2], a[buf][mi][3], ad);
            }
#pragma unroll
            for (int ni2 = 0; ni2 < 2; ni2++) {
                uint32_t bd = Bb + (uint32_t)((ks * 16 + lane15) * 272) +
                              (uint32_t)((wc + ni2 * 16 + lhi * 8) * 2);
                LDSM_X4_T(b[buf][ni2 * 2][0], b[buf][ni2 * 2][1],
                          b[buf][ni2 * 2 + 1][0], b[buf][ni2 * 2 + 1][1], bd);
            }
        };

        load_frag(0, 0);
#pragma unroll
        for (int ks = 0; ks < 2; ks++) {
            if (ks < 1) load_frag(1, 1);
#pragma unroll
            for (int mi = 0; mi < 4; mi++)
#pragma unroll
                for (int ni = 0; ni < 4; ni++)
                    MMA_F16(acc[mi][ni], a[ks][mi], b[ks][ni]);
        }
    }

    // epilogue
#pragma unroll
    for (int mi = 0; mi < 4; mi++) {
#pragma unroll
        for (int half = 0; half < 2; half++) {
            int r = wr + mi * 16 + gid + 8 * half;
            int slot = rt * BM + r;
            if (slot < count) {
                int s = toks[r];
                float w = wsh[r];
                float* o = out + (size_t)s * MDIM + nb + wc + tg * 2;
#pragma unroll
                for (int ni = 0; ni < 4; ni++) {
                    float2 v;
                    v.x = acc[mi][ni][half * 2 + 0] * w;
                    v.y = acc[mi][ni][half * 2 + 1] * w;
                    *reinterpret_cast<float2*>(o + ni * 8) = v;
                }
            }
        }
    }
}

// ---------------- launch -----------------------------------------------------
extern "C" void kernel_launch(void* const* d_in, const int* in_sizes, int n_in,
                              void* d_out, int out_size) {
    const float* x  = (const float*)d_in[0];
    const float* wg = (const float*)d_in[1];
    const float* we = (const float*)d_in[2];
    float* out = (float*)d_out;

    cudaFuncSetAttribute(moe_gemm, cudaFuncAttributeMaxDynamicSharedMemorySize,
                         SMEM_DYN);

    gate_cvt_kernel<<<GATE_BLKS + CVT_BLKS, 256>>>(x, wg, we);
    scan_kernel<<<1, 256>>>(out, (long)out_size > (long)S_TOK * MDIM ? 1 : 0);
    dim3 g(MDIM / BN, CAP / BM, NEXP);
    moe_gemm<<<g, 256, SMEM_DYN>>>(out);
}

// round 9
// speedup vs baseline: 1.3061x; 1.0650x over previous
#include <cuda_runtime.h>
#include <cuda_fp16.h>
#include <cstdint>

#define S_TOK 4096
#define MDIM  1024
#define NEXP  8
#define CAP   1024

#define BM 128
#define BN 128
#define BK 64
#define NST 3

#define A_BYTES (BM * 128)       // 128 rows x 64 fp16 (128B, Swizzle<3,4,3>)
#define B_BYTES (BK * 272)       // 64 rows x 128 fp16 + 16B pad (272B rows)
#define STG_BYTES (A_BYTES + B_BYTES)   // 33792
#define SMEM_DYN (NST * STG_BYTES + 1024)   // 102400

#define GATE_BLKS 256
#define CVT_BLKS  768

// ---------------- scratch ----------------------------------------------------
__device__ int    g_idx0[S_TOK];
__device__ float  g_wtop[S_TOK];
__device__ float  g_gates[S_TOK * NEXP];
__device__ int    g_perm[NEXP * CAP];
__device__ int    g_cnt[NEXP];
__device__ __half g_xh[S_TOK * MDIM];                  // fp16 x (8MB)
__device__ __half g_weh[(size_t)NEXP * MDIM * MDIM];   // fp16 we (16MB)

// ---------------- helpers ---------------------------------------------------
__device__ __forceinline__ uint32_t smem_u32(const void* p) {
    uint32_t a;
    asm("{ .reg .u64 t; cvta.to.shared.u64 t, %1; cvt.u32.u64 %0, t; }" : "=r"(a) : "l"(p));
    return a;
}

#define CP_ASYNC16(dst, src) \
    asm volatile("cp.async.cg.shared.global [%0], [%1], 16;" :: "r"(dst), "l"(src) : "memory")
#define CP_COMMIT() asm volatile("cp.async.commit_group;" ::: "memory")
#define CP_WAIT1()  asm volatile("cp.async.wait_group 1;" ::: "memory")

#define LDSM_X4(r0, r1, r2, r3, addr)                                          \
    asm volatile("ldmatrix.sync.aligned.m8n8.x4.shared.b16 {%0,%1,%2,%3}, [%4];" \
        : "=r"(r0), "=r"(r1), "=r"(r2), "=r"(r3) : "r"(addr))
#define LDSM_X4_T(r0, r1, r2, r3, addr)                                        \
    asm volatile("ldmatrix.sync.aligned.m8n8.x4.trans.shared.b16 {%0,%1,%2,%3}, [%4];" \
        : "=r"(r0), "=r"(r1), "=r"(r2), "=r"(r3) : "r"(addr))

#define MMA_F16(c, a, b)                                                       \
    asm volatile(                                                              \
        "mma.sync.aligned.m16n8k16.row.col.f32.f16.f16.f32 "                   \
        "{%0,%1,%2,%3},{%4,%5,%6,%7},{%8,%9},{%0,%1,%2,%3};\n"                 \
        : "+f"((c)[0]), "+f"((c)[1]), "+f"((c)[2]), "+f"((c)[3])               \
        : "r"((a)[0]), "r"((a)[1]), "r"((a)[2]), "r"((a)[3]),                  \
          "r"((b)[0]), "r"((b)[1]))

// ---------------- kernel 1: fused gate (blocks 0..255) + we->fp16 (rest) -----
__global__ void gate_cvt_kernel(const float* __restrict__ x,
                                const float* __restrict__ wg,
                                const float* __restrict__ we) {
    int tid = threadIdx.x;

    if (blockIdx.x >= GATE_BLKS) {
        size_t n4 = (size_t)NEXP * MDIM * MDIM / 4;
        size_t stride = (size_t)CVT_BLKS * 256;
        for (size_t i = (size_t)(blockIdx.x - GATE_BLKS) * 256 + tid; i < n4;
             i += stride) {
            float4 v = reinterpret_cast<const float4*>(we)[i];
            __half2 ha = __floats2half2_rn(v.x, v.y);
            __half2 hb = __floats2half2_rn(v.z, v.w);
            uint2 p;
            p.x = *reinterpret_cast<uint32_t*>(&ha);
            p.y = *reinterpret_cast<uint32_t*>(&hb);
            reinterpret_cast<uint2*>(g_weh)[i] = p;
        }
        return;
    }

    int warp = tid >> 5, lane = tid & 31;
    int s0 = blockIdx.x * 16 + warp * 2;

    float acc[NEXP][2];
#pragma unroll
    for (int e = 0; e < NEXP; e++) { acc[e][0] = 0.f; acc[e][1] = 0.f; }

    const float4* xr0 = reinterpret_cast<const float4*>(x + (size_t)s0 * MDIM);
    const float4* xr1 = reinterpret_cast<const float4*>(x + (size_t)(s0 + 1) * MDIM);
    uint2* xo0 = reinterpret_cast<uint2*>(g_xh + (size_t)s0 * MDIM);
    uint2* xo1 = reinterpret_cast<uint2*>(g_xh + (size_t)(s0 + 1) * MDIM);
#pragma unroll
    for (int i = 0; i < 8; i++) {
        int k4 = i * 32 + lane;
        float4 x0 = xr0[k4], x1 = xr1[k4];
        {
            __half2 a0 = __floats2half2_rn(x0.x, x0.y);
            __half2 b0 = __floats2half2_rn(x0.z, x0.w);
            uint2 p0; p0.x = *reinterpret_cast<uint32_t*>(&a0);
            p0.y = *reinterpret_cast<uint32_t*>(&b0);
            xo0[k4] = p0;
            __half2 a1 = __floats2half2_rn(x1.x, x1.y);
            __half2 b1 = __floats2half2_rn(x1.z, x1.w);
            uint2 p1; p1.x = *reinterpret_cast<uint32_t*>(&a1);
            p1.y = *reinterpret_cast<uint32_t*>(&b1);
            xo1[k4] = p1;
        }
#pragma unroll
        for (int e = 0; e < NEXP; e++) {
            float4 wv = reinterpret_cast<const float4*>(wg + e * MDIM)[k4];
            acc[e][0] += x0.x * wv.x + x0.y * wv.y + x0.z * wv.z + x0.w * wv.w;
            acc[e][1] += x1.x * wv.x + x1.y * wv.y + x1.z * wv.z + x1.w * wv.w;
        }
    }
#pragma unroll
    for (int e = 0; e < NEXP; e++) {
#pragma unroll
        for (int off = 16; off > 0; off >>= 1) {
            acc[e][0] += __shfl_xor_sync(0xffffffffu, acc[e][0], off);
            acc[e][1] += __shfl_xor_sync(0xffffffffu, acc[e][1], off);
        }
    }

    if (lane < 2) {
        int s = s0 + lane;
        float a[NEXP];
#pragma unroll
        for (int e = 0; e < NEXP; e++) a[e] = acc[e][lane];
        float mx = a[0];
        int am = 0;
#pragma unroll
        for (int e = 1; e < NEXP; e++)
            if (a[e] > mx) { mx = a[e]; am = e; }   // first-max = lowest idx on ties
        float g[NEXP];
        float sum = 0.f;
#pragma unroll
        for (int e = 0; e < NEXP; e++) { g[e] = expf(a[e] - mx); sum += g[e]; }
        float inv = 1.f / sum;
        g_idx0[s] = am;
        g_wtop[s] = g[am] * inv;
#pragma unroll
        for (int e = 0; e < NEXP; e++) g_gates[s * NEXP + e] = g[e] * inv;
    }
}

// ---------------- kernel 2: scan + perm + loss + drop-zero -------------------
__global__ void scan_kernel(float* __restrict__ out, int write_loss) {
    __shared__ unsigned char sidx[S_TOK];
    __shared__ int counts[256][9];
    __shared__ float mesh[256][9];
    __shared__ float me_f[NEXP];
    __shared__ int raw_cnt[NEXP];
    __shared__ int droplist[64];
    __shared__ int sh_drop;
    int tid = threadIdx.x;
    int wid = tid >> 5, lane = tid & 31;
    if (tid == 0) sh_drop = 0;

    for (int i = tid; i < S_TOK; i += 256)
        sidx[i] = (unsigned char)g_idx0[i];

    {
        float me8[NEXP];
#pragma unroll
        for (int e = 0; e < NEXP; e++) me8[e] = 0.f;
        int base = tid * 16;
        for (int j = 0; j < 16; j++) {
            const float* gp = g_gates + (size_t)(base + j) * NEXP;
#pragma unroll
            for (int e = 0; e < NEXP; e++) me8[e] += gp[e];
        }
#pragma unroll
        for (int e = 0; e < NEXP; e++) mesh[tid][e] = me8[e];
    }
    __syncthreads();

    int base = tid * 16;
    {
        int c8[NEXP];
#pragma unroll
        for (int e = 0; e < NEXP; e++) c8[e] = 0;
#pragma unroll
        for (int j = 0; j < 16; j++) c8[sidx[base + j]]++;
#pragma unroll
        for (int e = 0; e < NEXP; e++) counts[tid][e] = c8[e];
    }
    __syncthreads();

    {
        int e = wid;
        int run = 0;
        float msum = 0.f;
#pragma unroll
        for (int c = 0; c < 8; c++) {
            int t = c * 32 + lane;
            int v = counts[t][e];
            msum += mesh[t][e];
            int s = v;
#pragma unroll
            for (int off = 1; off < 32; off <<= 1) {
                int n = __shfl_up_sync(0xffffffffu, s, off);
                if (lane >= off) s += n;
            }
            counts[t][e] = run + s - v;
            run += __shfl_sync(0xffffffffu, s, 31);
        }
#pragma unroll
        for (int off = 16; off > 0; off >>= 1)
            msum += __shfl_xor_sync(0xffffffffu, msum, off);
        if (lane == 0) {
            raw_cnt[e] = run;
            g_cnt[e] = run < CAP ? run : CAP;
            me_f[e] = msum;
        }
    }
    __syncthreads();

    {
        int off[NEXP];
#pragma unroll
        for (int e = 0; e < NEXP; e++) off[e] = counts[tid][e];
#pragma unroll
        for (int j = 0; j < 16; j++) {
            int s2 = base + j;
            int e = sidx[s2];
            int c = off[e]++;
            if (c < CAP) {
                g_perm[e * CAP + c] = s2;
            } else {
                int p = atomicAdd(&sh_drop, 1);
                if (p < 64) droplist[p] = s2;
            }
        }
    }
    __syncthreads();

    if (tid == 0 && write_loss) {
        float l = 0.f;
#pragma unroll
        for (int e = 0; e < NEXP; e++) l += me_f[e] * (float)raw_cnt[e];
        out[(size_t)S_TOK * MDIM] =
            l * ((float)NEXP / ((float)S_TOK * (float)S_TOK));
    }

    int nd = sh_drop < 64 ? sh_drop : 64;
    for (int i = 0; i < nd; i++) {
        float* row = out + (size_t)droplist[i] * MDIM;
        float4 z = make_float4(0.f, 0.f, 0.f, 0.f);
        for (int j = tid; j < MDIM / 4; j += 256)
            reinterpret_cast<float4*>(row)[j] = z;
    }
}

// ---------------- kernel 3: gathered grouped GEMM (fp16, BK=64, NST=3) -------
__global__ void __launch_bounds__(256, 2)
moe_gemm(float* __restrict__ out) {
    extern __shared__ char smem[];
    int*   toks = reinterpret_cast<int*>(smem + NST * STG_BYTES);
    float* wsh  = reinterpret_cast<float*>(smem + NST * STG_BYTES + 512);

    int e = blockIdx.z, rt = blockIdx.y;
    int count = g_cnt[e];
    if (rt * BM >= count) return;
    int nb = blockIdx.x * BN;
    int tid = threadIdx.x;

    if (tid < BM) {
        int slot = rt * BM + tid;
        int s = (slot < count) ? g_perm[e * CAP + slot] : 0;
        toks[tid] = s;
        wsh[tid] = (slot < count) ? g_wtop[s] : 0.f;
    }
    __syncthreads();

    const __half* weh = g_weh + (size_t)e * MDIM * MDIM;
    uint32_t smA = smem_u32(smem);

    int atok[4];
#pragma unroll
    for (int p = 0; p < 4; p++) atok[p] = toks[(tid + 256 * p) >> 3];

    // cp.async per stage: 8 chunks of 16B per thread
    //  i<4 : A chunk (m = u>>3, q = u&7) -> 128B rows, Swizzle<3,4,3>
    //  i>=4: B chunk (k = v>>4, j = v&15) -> 272B rows
    auto issue_stage = [&](int kt, int st) {
        uint32_t Ab = smA + (uint32_t)(st * STG_BYTES);
        uint32_t Bb = Ab + A_BYTES;
        int k0 = kt * BK;
#pragma unroll
        for (int i = 0; i < 8; i++) {
            int u = tid + 256 * i;
            if (i < 4) {
                int m = u >> 3, q = u & 7;
                const __half* src = g_xh + (size_t)atok[i] * MDIM + k0 + q * 8;
                uint32_t dst = Ab + (uint32_t)(m * 128) +
                               (uint32_t)((q ^ (m & 7)) << 4);
                CP_ASYNC16(dst, src);
            } else {
                int v = u - 1024;
                int k = v >> 4, j = v & 15;
                const __half* src = weh + (size_t)(k0 + k) * MDIM + nb + j * 8;
                uint32_t dst = Bb + (uint32_t)(k * 272 + j * 16);
                CP_ASYNC16(dst, src);
            }
        }
    };

    int warp = tid >> 5, lane = tid & 31;
    int gid = lane >> 2, tg = lane & 3;
    int wr = (warp & 1) * 64;
    int wc = (warp >> 1) * 32;
    int lane15 = lane & 15, lhi = lane >> 4;

    float acc[4][4][4];
#pragma unroll
    for (int mi = 0; mi < 4; mi++)
#pragma unroll
        for (int ni = 0; ni < 4; ni++)
#pragma unroll
            for (int r = 0; r < 4; r++) acc[mi][ni][r] = 0.f;

    const int NKT = MDIM / BK;   // 16

    issue_stage(0, 0); CP_COMMIT();
    issue_stage(1, 1); CP_COMMIT();

    for (int kt = 0; kt < NKT; kt++) {
        CP_WAIT1();
        __syncthreads();
        if (kt + 2 < NKT) issue_stage(kt + 2, (kt + 2) % NST);
        CP_COMMIT();

        int st = kt % NST;
        uint32_t Ab = smA + (uint32_t)(st * STG_BYTES);
        uint32_t Bb = Ab + A_BYTES;

        uint32_t a[2][4][4], b[2][4][2];
        auto load_frag = [&](int ks, int buf) {
            int qq = ks * 2 + lhi;              // logical 16B chunk (0..7)
#pragma unroll
            for (int mi = 0; mi < 4; mi++) {
                int row = wr + mi * 16 + lane15;
                uint32_t ad = Ab + (uint32_t)(row * 128) +
                              (uint32_t)((qq ^ (row & 7)) << 4);
                LDSM_X4(a[buf][mi][0], a[buf][mi][1], a[buf][mi][2], a[buf][mi][3], ad);
            }
#pragma unroll
            for (int ni2 = 0; ni2 < 2; ni2++) {
                uint32_t bd = Bb + (uint32_t)((ks * 16 + lane15) * 272) +
                              (uint32_t)((wc + ni2 * 16 + lhi * 8) * 2);
                LDSM_X4_T(b[buf][ni2 * 2][0], b[buf][ni2 * 2][1],
                          b[buf][ni2 * 2 + 1][0], b[buf][ni2 * 2 + 1][1], bd);
            }
        };

        load_frag(0, 0);
#pragma unroll
        for (int ks = 0; ks < 4; ks++) {
            if (ks < 3) load_frag(ks + 1, (ks + 1) & 1);
#pragma unroll
            for (int mi = 0; mi < 4; mi++)
#pragma unroll
                for (int ni = 0; ni < 4; ni++)
                    MMA_F16(acc[mi][ni], a[ks & 1][mi], b[ks & 1][ni]);
        }
    }

    // epilogue
#pragma unroll
    for (int mi = 0; mi < 4; mi++) {
#pragma unroll
        for (int half = 0; half < 2; half++) {
            int r = wr + mi * 16 + gid + 8 * half;
            int slot = rt * BM + r;
            if (slot < count) {
                int s = toks[r];
                float w = wsh[r];
                float* o = out + (size_t)s * MDIM + nb + wc + tg * 2;
#pragma unroll
                for (int ni = 0; ni < 4; ni++) {
                    float2 v;
                    v.x = acc[mi][ni][half * 2 + 0] * w;
                    v.y = acc[mi][ni][half * 2 + 1] * w;
                    *reinterpret_cast<float2*>(o + ni * 8) = v;
                }
            }
        }
    }
}

// ---------------- launch -----------------------------------------------------
extern "C" void kernel_launch(void* const* d_in, const int* in_sizes, int n_in,
                              void* d_out, int out_size) {
    const float* x  = (const float*)d_in[0];
    const float* wg = (const float*)d_in[1];
    const float* we = (const float*)d_in[2];
    float* out = (float*)d_out;

    cudaFuncSetAttribute(moe_gemm, cudaFuncAttributeMaxDynamicSharedMemorySize,
                         SMEM_DYN);

    gate_cvt_kernel<<<GATE_BLKS + CVT_BLKS, 256>>>(x, wg, we);
    scan_kernel<<<1, 256>>>(out, (long)out_size > (long)S_TOK * MDIM ? 1 : 0);
    dim3 g(MDIM / BN, CAP / BM, NEXP);
    moe_gemm<<<g, 256, SMEM_DYN>>>(out);
}